// round 11
// baseline (speedup 1.0000x reference)
#include <cuda_runtime.h>
#include <cstdint>

// out[b,n,m] = sum_e A[b,n,e]*B[b,m,e]; b=8, n=m=2048, e=1024, fp32.
// Single kernel: TF32 mma.m16n8k8, 3-stage cp.async, fragment double-buffer
// with cross-chunk prefetch; cvt.rna.tf32 in the (slack-covered) prefetch
// path. CTA tile 128x256, 8 warps, warp tile 64x64, BK=32.

static constexpr int DN = 2048, DM = 2048, DE = 1024;
static constexpr int BK = 32, NCHUNK = DE / BK;

static constexpr unsigned A_PLANE = 128u * 128u;          // 16 KB
static constexpr unsigned B_PLANE = 256u * 128u;          // 32 KB
static constexpr unsigned STAGE   = A_PLANE + B_PLANE;    // 48 KB
static constexpr int      NSTAGE  = 3;
static constexpr unsigned SMEM_TOTAL = (unsigned)NSTAGE * STAGE;  // 144 KB

__device__ __forceinline__ unsigned smem_u32(const void* p) {
    unsigned a;
    asm("{ .reg .u64 t; cvta.to.shared.u64 t, %1; cvt.u32.u64 %0, t; }" : "=r"(a) : "l"(p));
    return a;
}

#define LDSM4(r0, r1, r2, r3, addr) \
    asm volatile("ldmatrix.sync.aligned.m8n8.x4.shared.b16 {%0,%1,%2,%3}, [%4];" \
                 : "=r"(r0), "=r"(r1), "=r"(r2), "=r"(r3) : "r"(addr))

#define MMA_TF32(d, a, b) \
    asm volatile("mma.sync.aligned.m16n8k8.row.col.f32.tf32.tf32.f32 " \
                 "{%0,%1,%2,%3},{%4,%5,%6,%7},{%8,%9},{%0,%1,%2,%3};" \
                 : "+f"((d)[0]), "+f"((d)[1]), "+f"((d)[2]), "+f"((d)[3]) \
                 : "r"((a)[0]), "r"((a)[1]), "r"((a)[2]), "r"((a)[3]), \
                   "r"((b)[0]), "r"((b)[1]))

#define CVT_TF32(x) asm volatile("cvt.rna.tf32.f32 %0, %0;" : "+r"(x))

#define CPASYNC16(dst, src) \
    asm volatile("cp.async.cg.shared.global [%0], [%1], 16;" :: "r"(dst), "l"(src))

// A tile: 128 rows x 32 fp32; B tile: 256 rows x 32 fp32; row = 128 B contig.
// smem swizzle: phys idx16 = idx ^ (row & 7).
__device__ __forceinline__ void issue_stage(const float* __restrict__ aT,
                                            const float* __restrict__ bT,
                                            unsigned stg, unsigned tid) {
#pragma unroll
    for (int g = 0; g < 4; ++g) {                  // A: 1024 16-B units
        unsigned u = tid + (unsigned)g * 256u;
        unsigned row = u >> 3, idx = u & 7u;
        unsigned dst = stg + row * 128u + 16u * (idx ^ (row & 7u));
        CPASYNC16(dst, (const void*)(aT + (size_t)row * DE + idx * 4u));
    }
#pragma unroll
    for (int g = 0; g < 8; ++g) {                  // B: 2048 16-B units
        unsigned u = tid + (unsigned)g * 256u;
        unsigned row = u >> 3, idx = u & 7u;
        unsigned dst = stg + A_PLANE + row * 128u + 16u * (idx ^ (row & 7u));
        CPASYNC16(dst, (const void*)(bT + (size_t)row * DE + idx * 4u));
    }
}

// LDSM + tf32-round; sits in the one-step-ahead prefetch path.
__device__ __forceinline__ void load_frags(unsigned stg, int s,
                                           int wm, int wn,
                                           int a_r, int a_sel, int b_r, int b_sel,
                                           unsigned af[4][4], unsigned bf[8][2]) {
    const unsigned sA = stg, sB = stg + A_PLANE;
#pragma unroll
    for (int jj = 0; jj < 4; ++jj) {
        const unsigned row = (unsigned)(wn + 16 * jj + b_r);
        LDSM4(bf[2*jj][0], bf[2*jj][1], bf[2*jj+1][0], bf[2*jj+1][1],
              sB + row * 128u + 16u * ((unsigned)(2*s + b_sel) ^ (row & 7u)));
    }
#pragma unroll
    for (int i = 0; i < 4; ++i) {
        const unsigned row = (unsigned)(wm + 16 * i + a_r);
        LDSM4(af[i][0], af[i][1], af[i][2], af[i][3],
              sA + row * 128u + 16u * ((unsigned)(2*s + a_sel) ^ (row & 7u)));
    }
#pragma unroll
    for (int i = 0; i < 4; ++i) {
        CVT_TF32(af[i][0]); CVT_TF32(af[i][1]);
        CVT_TF32(af[i][2]); CVT_TF32(af[i][3]);
    }
#pragma unroll
    for (int j = 0; j < 8; ++j) { CVT_TF32(bf[j][0]); CVT_TF32(bf[j][1]); }
}

__global__ void __launch_bounds__(256, 1)
bmm_tf32_kernel(const float* __restrict__ A, const float* __restrict__ B,
                float* __restrict__ out) {
    extern __shared__ char smem[];
    const unsigned sbase = smem_u32(smem);
    const unsigned tid = threadIdx.x;
    const int wid = (int)(tid >> 5), lane = (int)(tid & 31);
    const int bb = blockIdx.y;
    const int m0 = (int)(blockIdx.x >> 3) * 128;
    const int n0 = (int)(blockIdx.x & 7) * 256;

    const float* aTile = A + ((size_t)(bb * DN + m0)) * DE;
    const float* bTile = B + ((size_t)(bb * DM + n0)) * DE;

    // warp grid 2(M) x 4(N); warp tile 64 x 64
    const int wm = (wid >> 2) * 64, wn = (wid & 3) * 64;
    const int a_r   = lane & 15;
    const int a_sel = (lane >> 4) & 1;
    const int b_r   = (lane & 7) + ((lane >> 4) << 3);
    const int b_sel = (lane >> 3) & 1;

    float acc[4][8][4];
#pragma unroll
    for (int i = 0; i < 4; ++i)
#pragma unroll
        for (int j = 0; j < 8; ++j)
#pragma unroll
            for (int c = 0; c < 4; ++c) acc[i][j][c] = 0.0f;

    // prologue: stages 0,1 complete+visible; stage 2 in flight; step0 frags up
    issue_stage(aTile,      bTile,      sbase,         tid);
    asm volatile("cp.async.commit_group;" ::: "memory");
    issue_stage(aTile + BK, bTile + BK, sbase + STAGE, tid);
    asm volatile("cp.async.commit_group;" ::: "memory");
    asm volatile("cp.async.wait_group 0;" ::: "memory");
    __syncthreads();
    issue_stage(aTile + 2 * BK, bTile + 2 * BK, sbase + 2u * STAGE, tid);
    asm volatile("cp.async.commit_group;" ::: "memory");

    unsigned af[2][4][4], bf[2][8][2];
    load_frags(sbase, 0, wm, wn, a_r, a_sel, b_r, b_sel, af[0], bf[0]);

    unsigned slot_cur = 0;                 // kc % 3
    for (int kc = 0; kc < NCHUNK; ++kc) {
        const unsigned stg  = sbase + slot_cur * STAGE;
        unsigned slot_nxt = slot_cur + 1u; if (slot_nxt >= (unsigned)NSTAGE) slot_nxt = 0;
        const unsigned stgn = sbase + slot_nxt * STAGE;

#pragma unroll
        for (int s = 0; s < 4; ++s) {      // compile-time s => no spills
            if (s < 3) {
                load_frags(stg, s + 1, wm, wn, a_r, a_sel, b_r, b_sel,
                           af[(s + 1) & 1], bf[(s + 1) & 1]);
            } else if (kc + 1 < NCHUNK) {
                // step 0 of next chunk from stage kc+1 (visible since last sync2)
                load_frags(stgn, 0, wm, wn, a_r, a_sel, b_r, b_sel,
                           af[0], bf[0]);
            }
#pragma unroll
            for (int i = 0; i < 4; ++i)
#pragma unroll
                for (int j = 0; j < 8; ++j)
                    MMA_TF32(acc[i][j], af[s & 1][i], bf[s & 1][j]);
        }

        if (kc + 1 < NCHUNK) {
            __syncthreads();               // sync1: slot kc%3 free to overwrite
            if (kc + 3 < NCHUNK) {
                issue_stage(aTile + (kc + 3) * BK, bTile + (kc + 3) * BK,
                            stg, tid);     // reuse the vacated slot
                asm volatile("cp.async.commit_group;" ::: "memory");
                asm volatile("cp.async.wait_group 1;" ::: "memory"); // kc+2 done
            } else {
                asm volatile("cp.async.wait_group 0;" ::: "memory");
            }
            __syncthreads();               // sync2: stage kc+2 visible
        }
        slot_cur = slot_nxt;
    }

    // epilogue: direct float2 global stores
    {
        const int r0 = wm + (lane >> 2);
        const int c0 = wn + 2 * (lane & 3);
        float* obase = out + ((size_t)(bb * DN) + (size_t)m0) * DM + n0;
#pragma unroll
        for (int i = 0; i < 4; ++i)
#pragma unroll
            for (int j = 0; j < 8; ++j) {
                float* p0 = obase + (size_t)(r0 + 16*i) * DM + (c0 + 8*j);
                reinterpret_cast<float2*>(p0)[0] = make_float2(acc[i][j][0], acc[i][j][1]);
                float* p1 = p0 + 8 * DM;
                reinterpret_cast<float2*>(p1)[0] = make_float2(acc[i][j][2], acc[i][j][3]);
            }
    }
}

extern "C" void kernel_launch(void* const* d_in, const int* in_sizes, int n_in,
                              void* d_out, int out_size) {
    const float* A = (const float*)d_in[0];
    const float* B = (const float*)d_in[1];
    float* out = (float*)d_out;
    cudaFuncSetAttribute(bmm_tf32_kernel,
                         cudaFuncAttributeMaxDynamicSharedMemorySize, (int)SMEM_TOTAL);
    dim3 grid(128, 8);   // 16(M) x 8(N) tiles per batch, 8 batches
    bmm_tf32_kernel<<<grid, 256, SMEM_TOTAL>>>(A, B, out);
}

// round 13
// speedup vs baseline: 1.3413x; 1.3413x over previous
#include <cuda_runtime.h>
#include <cstdint>

// out[b,n,m] = sum_e A[b,n,e]*B[b,m,e]; b=8, n=m=2048, e=1024, fp32.
// Pass 1: stream-round inputs to tf32 (rna) into scratch.
// Pass 2: TF32 mma.m16n8k8, 4-stage cp.async pipeline, ONE barrier per
// chunk (issue -> wait_group 1 -> sync), fragment double-buffer with
// cross-chunk prefetch. CTA tile 128x256, 8 warps, warp tile 64x64, BK=32.

static constexpr int DN = 2048, DM = 2048, DE = 1024;
static constexpr int BK = 32, NCHUNK = DE / BK;

static constexpr size_t MAT_ELEMS = (size_t)8 * 2048 * 1024;
__device__ __align__(128) float g_tf32[2 * MAT_ELEMS];          // 128 MB

static constexpr unsigned A_PLANE = 128u * 128u;          // 16 KB
static constexpr unsigned B_PLANE = 256u * 128u;          // 32 KB
static constexpr unsigned STAGE   = A_PLANE + B_PLANE;    // 48 KB
static constexpr int      NSTAGE  = 4;
static constexpr unsigned SMEM_TOTAL = (unsigned)NSTAGE * STAGE;  // 192 KB

__device__ __forceinline__ unsigned smem_u32(const void* p) {
    unsigned a;
    asm("{ .reg .u64 t; cvta.to.shared.u64 t, %1; cvt.u32.u64 %0, t; }" : "=r"(a) : "l"(p));
    return a;
}

#define LDSM4(r0, r1, r2, r3, addr) \
    asm volatile("ldmatrix.sync.aligned.m8n8.x4.shared.b16 {%0,%1,%2,%3}, [%4];" \
                 : "=r"(r0), "=r"(r1), "=r"(r2), "=r"(r3) : "r"(addr))

#define MMA_TF32(d, a, b) \
    asm volatile("mma.sync.aligned.m16n8k8.row.col.f32.tf32.tf32.f32 " \
                 "{%0,%1,%2,%3},{%4,%5,%6,%7},{%8,%9},{%0,%1,%2,%3};" \
                 : "+f"((d)[0]), "+f"((d)[1]), "+f"((d)[2]), "+f"((d)[3]) \
                 : "r"((a)[0]), "r"((a)[1]), "r"((a)[2]), "r"((a)[3]), \
                   "r"((b)[0]), "r"((b)[1]))

#define CPASYNC16(dst, src) \
    asm volatile("cp.async.cg.shared.global [%0], [%1], 16;" :: "r"(dst), "l"(src))

// ---------------------------------------------------------------------------
// Pass 1: tf32-round (rna) every element. 16 floats per thread.
// ---------------------------------------------------------------------------
__global__ void __launch_bounds__(256)
tf32_prepass(const float* __restrict__ A, const float* __restrict__ B) {
    const size_t gid = (size_t)blockIdx.x * 256u + threadIdx.x;
    const unsigned mat = (unsigned)(gid >> 20);
    const size_t off = (gid & ((1u << 20) - 1u)) * 16u;
    const float4* src = reinterpret_cast<const float4*>((mat ? B : A) + off);
    float4* dst = reinterpret_cast<float4*>(g_tf32 + mat * MAT_ELEMS + off);
#pragma unroll
    for (int i = 0; i < 4; ++i) {
        float4 v = src[i];
        asm("cvt.rna.tf32.f32 %0, %0;" : "+f"(v.x));
        asm("cvt.rna.tf32.f32 %0, %0;" : "+f"(v.y));
        asm("cvt.rna.tf32.f32 %0, %0;" : "+f"(v.z));
        asm("cvt.rna.tf32.f32 %0, %0;" : "+f"(v.w));
        dst[i] = v;
    }
}

// ---------------------------------------------------------------------------
// Pass 2
// ---------------------------------------------------------------------------
__device__ __forceinline__ void issue_stage(const float* __restrict__ aT,
                                            const float* __restrict__ bT,
                                            unsigned stg, unsigned tid) {
#pragma unroll
    for (int g = 0; g < 4; ++g) {                  // A: 1024 16-B units
        unsigned u = tid + (unsigned)g * 256u;
        unsigned row = u >> 3, idx = u & 7u;
        unsigned dst = stg + row * 128u + 16u * (idx ^ (row & 7u));
        CPASYNC16(dst, (const void*)(aT + (size_t)row * DE + idx * 4u));
    }
#pragma unroll
    for (int g = 0; g < 8; ++g) {                  // B: 2048 16-B units
        unsigned u = tid + (unsigned)g * 256u;
        unsigned row = u >> 3, idx = u & 7u;
        unsigned dst = stg + A_PLANE + row * 128u + 16u * (idx ^ (row & 7u));
        CPASYNC16(dst, (const void*)(bT + (size_t)row * DE + idx * 4u));
    }
}

__device__ __forceinline__ void load_frags(unsigned stg, int s,
                                           int wm, int wn,
                                           int a_r, int a_sel, int b_r, int b_sel,
                                           unsigned af[4][4], unsigned bf[8][2]) {
    const unsigned sA = stg, sB = stg + A_PLANE;
#pragma unroll
    for (int jj = 0; jj < 4; ++jj) {
        const unsigned row = (unsigned)(wn + 16 * jj + b_r);
        LDSM4(bf[2*jj][0], bf[2*jj][1], bf[2*jj+1][0], bf[2*jj+1][1],
              sB + row * 128u + 16u * ((unsigned)(2*s + b_sel) ^ (row & 7u)));
    }
#pragma unroll
    for (int i = 0; i < 4; ++i) {
        const unsigned row = (unsigned)(wm + 16 * i + a_r);
        LDSM4(af[i][0], af[i][1], af[i][2], af[i][3],
              sA + row * 128u + 16u * ((unsigned)(2*s + a_sel) ^ (row & 7u)));
    }
}

__global__ void __launch_bounds__(256, 1)
bmm_tf32_kernel(float* __restrict__ out) {
    extern __shared__ char smem[];
    const unsigned sbase = smem_u32(smem);
    const unsigned tid = threadIdx.x;
    const int wid = (int)(tid >> 5), lane = (int)(tid & 31);
    const int bb = blockIdx.y;
    const int m0 = (int)(blockIdx.x >> 3) * 128;
    const int n0 = (int)(blockIdx.x & 7) * 256;

    const float* aTile = g_tf32 + ((size_t)(bb * DN + m0)) * DE;
    const float* bTile = g_tf32 + MAT_ELEMS + ((size_t)(bb * DM + n0)) * DE;

    // warp grid 2(M) x 4(N); warp tile 64 x 64
    const int wm = (wid >> 2) * 64, wn = (wid & 3) * 64;
    const int a_r   = lane & 15;
    const int a_sel = (lane >> 4) & 1;
    const int b_r   = (lane & 7) + ((lane >> 4) << 3);
    const int b_sel = (lane >> 3) & 1;

    float acc[4][8][4];
#pragma unroll
    for (int i = 0; i < 4; ++i)
#pragma unroll
        for (int j = 0; j < 8; ++j)
#pragma unroll
            for (int c = 0; c < 4; ++c) acc[i][j][c] = 0.0f;

    // prologue: issue stages 0,1,2; stages 0,1 complete+visible after barrier
    issue_stage(aTile,          bTile,          sbase,              tid);
    asm volatile("cp.async.commit_group;" ::: "memory");
    issue_stage(aTile + BK,     bTile + BK,     sbase + STAGE,      tid);
    asm volatile("cp.async.commit_group;" ::: "memory");
    issue_stage(aTile + 2 * BK, bTile + 2 * BK, sbase + 2u * STAGE, tid);
    asm volatile("cp.async.commit_group;" ::: "memory");
    asm volatile("cp.async.wait_group 1;" ::: "memory");
    __syncthreads();

    unsigned af[2][4][4], bf[2][8][2];
    load_frags(sbase, 0, wm, wn, a_r, a_sel, b_r, b_sel, af[0], bf[0]);

    for (int kc = 0; kc < NCHUNK; ++kc) {
        const unsigned slot_cur = (unsigned)(kc & 3);
        const unsigned stg  = sbase + slot_cur * STAGE;
        const unsigned stgn = sbase + (unsigned)((kc + 1) & 3) * STAGE;

        if (kc > 0) {
            // issue stage kc+2 into slot (kc+2)%4 (readers finished 2 barriers ago)
            if (kc + 2 < NCHUNK) {
                issue_stage(aTile + (kc + 2) * BK, bTile + (kc + 2) * BK,
                            sbase + (unsigned)((kc + 2) & 3) * STAGE, tid);
                asm volatile("cp.async.commit_group;" ::: "memory");
                asm volatile("cp.async.wait_group 1;" ::: "memory"); // kc+1 done
            } else {
                asm volatile("cp.async.wait_group 0;" ::: "memory");
            }
            __syncthreads();               // stage kc+1 visible to all
        }

#pragma unroll
        for (int s = 0; s < 4; ++s) {      // compile-time s => no spills
            if (s < 3) {
                load_frags(stg, s + 1, wm, wn, a_r, a_sel, b_r, b_sel,
                           af[(s + 1) & 1], bf[(s + 1) & 1]);
            } else if (kc + 1 < NCHUNK) {
                // step 0 of next chunk from stage kc+1 (visible at this chunk's top)
                load_frags(stgn, 0, wm, wn, a_r, a_sel, b_r, b_sel,
                           af[0], bf[0]);
            }
#pragma unroll
            for (int i = 0; i < 4; ++i)
#pragma unroll
                for (int j = 0; j < 8; ++j)
                    MMA_TF32(acc[i][j], af[s & 1][i], bf[s & 1][j]);
        }
    }

    // epilogue: direct float2 global stores
    {
        const int r0 = wm + (lane >> 2);
        const int c0 = wn + 2 * (lane & 3);
        float* obase = out + ((size_t)(bb * DN) + (size_t)m0) * DM + n0;
#pragma unroll
        for (int i = 0; i < 4; ++i)
#pragma unroll
            for (int j = 0; j < 8; ++j) {
                float* p0 = obase + (size_t)(r0 + 16*i) * DM + (c0 + 8*j);
                reinterpret_cast<float2*>(p0)[0] = make_float2(acc[i][j][0], acc[i][j][1]);
                float* p1 = p0 + 8 * DM;
                reinterpret_cast<float2*>(p1)[0] = make_float2(acc[i][j][2], acc[i][j][3]);
            }
    }
}

extern "C" void kernel_launch(void* const* d_in, const int* in_sizes, int n_in,
                              void* d_out, int out_size) {
    const float* A = (const float*)d_in[0];
    const float* B = (const float*)d_in[1];
    float* out = (float*)d_out;

    tf32_prepass<<<8192, 256>>>(A, B);

    cudaFuncSetAttribute(bmm_tf32_kernel,
                         cudaFuncAttributeMaxDynamicSharedMemorySize, (int)SMEM_TOTAL);
    dim3 grid(128, 8);
    bmm_tf32_kernel<<<grid, 256, SMEM_TOTAL>>>(out);
}